// round 13
// baseline (speedup 1.0000x reference)
#include <cuda_runtime.h>
#include <cuda_bf16.h>
#include <cstdint>

#define N_NODES 50000
#define N_EDGES 1600000
#define NUM_FEATURES 500
#define HIDDEN 64
#define NUM_CLASSES 40
#define NUM_LAYERS 4
#define STEP_F 0.1f

#define SCAN_BLK 1024
#define SCAN_NBLK ((N_NODES + SCAN_BLK - 1) / SCAN_BLK)   // 49

// ---------------- device scratch (static, allocation-free) ----------------
__device__ float g_h[N_NODES * HIDDEN];
__device__ float g_x0[N_NODES * HIDDEN];
__device__ float g_agg[N_NODES * HIDDEN];
__device__ __align__(128) __nv_bfloat162 g_hbf[N_NODES * (HIDDEN / 2)];  // bf16 mirror of h
__device__ unsigned long long g_srccoef[N_EDGES];   // packed {src, coef}
__device__ int   g_rowptr[N_NODES + 1];
__device__ int   g_degcnt[N_NODES];
__device__ int   g_fill[N_NODES];
__device__ float g_deginv[N_NODES];
__device__ float g_W[HIDDEN * HIDDEN];
__device__ int   g_blocksums[SCAN_NBLK];
__device__ int   g_blockoff[SCAN_NBLK];

// ---------------- graph preprocessing ----------------
__global__ void zero_counts() {
    int i = blockIdx.x * blockDim.x + threadIdx.x;
    if (i < N_NODES) { g_degcnt[i] = 0; g_fill[i] = 0; }
}

__global__ void count_deg(const int* __restrict__ col) {
    int e = blockIdx.x * blockDim.x + threadIdx.x;
    if (e < N_EDGES) atomicAdd(&g_degcnt[col[e]], 1);
}

__global__ void deg_inv_kernel() {
    int i = blockIdx.x * blockDim.x + threadIdx.x;
    if (i < N_NODES) {
        int c = g_degcnt[i];
        g_deginv[i] = (c > 0) ? rsqrtf((float)c) : 0.0f;
    }
}

// ---- multi-block exclusive scan of g_degcnt -> g_rowptr ----
__global__ void scan1() {
    __shared__ int s[SCAN_BLK];
    int b = blockIdx.x, t = threadIdx.x;
    int i = b * SCAN_BLK + t;
    int v = (i < N_NODES) ? g_degcnt[i] : 0;
    s[t] = v;
    __syncthreads();
#pragma unroll
    for (int off = 1; off < SCAN_BLK; off <<= 1) {
        int tv = 0;
        if (t >= off) tv = s[t - off];
        __syncthreads();
        if (t >= off) s[t] += tv;
        __syncthreads();
    }
    if (i < N_NODES) g_rowptr[i] = s[t] - v;     // block-local exclusive
    if (t == SCAN_BLK - 1) g_blocksums[b] = s[t];
}

__global__ void scan2() {
    if (threadIdx.x == 0) {
        int run = 0;
        for (int b = 0; b < SCAN_NBLK; b++) {
            g_blockoff[b] = run;
            run += g_blocksums[b];
        }
        g_rowptr[N_NODES] = run;
    }
}

__global__ void scan3() {
    int i = blockIdx.x * blockDim.x + threadIdx.x;
    if (i < N_NODES) g_rowptr[i] += g_blockoff[i >> 10];
}

__global__ void fill_csr(const int* __restrict__ row, const int* __restrict__ col) {
    int e = blockIdx.x * blockDim.x + threadIdx.x;
    if (e >= N_EDGES) return;
    int v = col[e];
    int r = row[e];
    int slot = g_rowptr[v] + atomicAdd(&g_fill[v], 1);
    float cf = g_deginv[r] * g_deginv[v];
    g_srccoef[slot] = (unsigned long long)(unsigned)r
                    | ((unsigned long long)__float_as_uint(cf) << 32);
}

// ---------------- pairwise weight: W_eff = sym(triu(pw,1)) + diag(q*rowsum|W|+r)
__global__ void weff_kernel(const float* __restrict__ pw) {
    int i = threadIdx.x;
    if (i >= HIDDEN) return;
    float q  = pw[i * (HIDDEN + 2) + HIDDEN];
    float rr = pw[i * (HIDDEN + 2) + HIDDEN + 1];
    float s = 0.0f;
    for (int j = 0; j < HIDDEN; j++) {
        float w = 0.0f;
        if (i < j)      w = pw[i * (HIDDEN + 2) + j];
        else if (i > j) w = pw[j * (HIDDEN + 2) + i];
        s += fabsf(w);
        g_W[i * HIDDEN + j] = w;
    }
    g_W[i * HIDDEN + i] = q * s + rr;
}

// ---------------- edge aggregation: agg[v] = sum coef * h_bf16[src]
// one warp per node; 32 lanes cover the 64-bf16 row (128B = ONE cache line).
__global__ void gather_kernel() {
    int gw   = (blockIdx.x * blockDim.x + threadIdx.x) >> 5;
    int lane = threadIdx.x & 31;
    if (gw >= N_NODES) return;
    int beg = g_rowptr[gw];
    int end = g_rowptr[gw + 1];
    float2 acc = make_float2(0.0f, 0.0f);
    const __nv_bfloat162* __restrict__ hb = g_hbf;
    int e = beg;
    for (; e + 7 < end; e += 8) {
        unsigned long long p[8];
        __nv_bfloat162 b[8];
#pragma unroll
        for (int i = 0; i < 8; i++) p[i] = __ldg(&g_srccoef[e + i]);
#pragma unroll
        for (int i = 0; i < 8; i++)
            b[i] = __ldg(hb + (size_t)(unsigned)(p[i] & 0xffffffffu) * 32 + lane);
#pragma unroll
        for (int i = 0; i < 8; i++) {
            float cf = __uint_as_float((unsigned)(p[i] >> 32));
            float2 v = __bfloat1622float2(b[i]);
            acc.x += cf * v.x;
            acc.y += cf * v.y;
        }
    }
    for (; e < end; e++) {
        unsigned long long p0 = __ldg(&g_srccoef[e]);
        __nv_bfloat162 b0 = __ldg(hb + (size_t)(unsigned)(p0 & 0xffffffffu) * 32 + lane);
        float c0 = __uint_as_float((unsigned)(p0 >> 32));
        float2 v0 = __bfloat1622float2(b0);
        acc.x += c0 * v0.x; acc.y += c0 * v0.y;
    }
    *(float2*)(g_agg + (size_t)gw * HIDDEN + lane * 2) = acc;
}

// ---------------- tf32 tensor-core GEMM: C[M,N] = A[M,K] @ B[N,K]^T
// mma.sync.m16n8k8, 256 threads, warp grid 4(M)x2(N), warp tile 32x32.
// smem: As[m][BK+4], Bs[n][BK+4] (stride 20 words -> conflict-free frag loads).
// MODE 0: encoder (A=x, B=enc_w)   -> writes g_h, g_x0, g_hbf
// MODE 1: layer   (A=g_agg, B=g_W) -> g_h += STEP*relu(acc - h*ext + x0*beta); also g_hbf
// MODE 2: decoder (A=g_h, B=dec_w) -> writes Cout
#define BM 128
#define BN 64
#define BK 16
#define KS (BK + 4)    // smem k-stride (20 words)

__device__ __forceinline__ uint32_t cvt_tf32(float v) {
    uint32_t u;
    asm("cvt.rna.tf32.f32 %0, %1;" : "=r"(u) : "f"(v));
    return u;
}

#define MMA_TF32(d, a, b)                                              \
    asm volatile(                                                      \
        "mma.sync.aligned.m16n8k8.row.col.f32.tf32.tf32.f32 "          \
        "{%0,%1,%2,%3}, {%4,%5,%6,%7}, {%8,%9}, {%0,%1,%2,%3};"        \
        : "+f"(d[0]), "+f"(d[1]), "+f"(d[2]), "+f"(d[3])               \
        : "r"(a[0]), "r"(a[1]), "r"(a[2]), "r"(a[3]),                  \
          "r"(b[0]), "r"(b[1]))

__device__ __forceinline__ void store_bf2(int row, int col, float x, float y) {
    __nv_bfloat162 bb = __floats2bfloat162_rn(x, y);
    g_hbf[(size_t)row * 32 + (col >> 1)] = bb;
}

template <int MODE>
__global__ void __launch_bounds__(256)
gemm_mma(const float* __restrict__ Ap, const float* __restrict__ Bp,
         float* __restrict__ Cout,
         int M, int N, int K,
         const float* __restrict__ ext, const float* __restrict__ betap) {
    __shared__ __align__(16) uint32_t As[BM][KS];
    __shared__ __align__(16) uint32_t Bs[BN][KS];

    const float* A = (MODE == 0) ? Ap : ((MODE == 1) ? (const float*)g_agg : (const float*)g_h);
    const float* B = (MODE == 1) ? (const float*)g_W : Bp;

    int tid  = threadIdx.x;
    int warp = tid >> 5;
    int lane = tid & 31;
    int q = lane & 3;          // k-quad
    int g = lane >> 2;         // group row/col
    int warpM = warp & 3;      // 4 warps along M
    int warpN = warp >> 2;     // 2 warps along N
    int wm0 = warpM * 32;
    int wn0 = warpN * 32;
    int bm0 = blockIdx.x * BM;

    float d[2][4][4];
#pragma unroll
    for (int mt = 0; mt < 2; mt++)
#pragma unroll
        for (int nt = 0; nt < 4; nt++)
#pragma unroll
            for (int i = 0; i < 4; i++) d[mt][nt][i] = 0.0f;

    for (int kb = 0; kb < K; kb += BK) {
        // ---- stage A (128x16): 2 float4 per thread, cvt to tf32, STS.128
#pragma unroll
        for (int it = 0; it < 2; it++) {
            int j = tid + it * 256;          // 0..511 float4 slots
            int arow = j >> 2;
            int kc4 = (j & 3) * 4;
            int grow = bm0 + arow;
            float4 v = make_float4(0.f, 0.f, 0.f, 0.f);
            if (grow < M) {
                if (kb + kc4 + 3 < K) {
                    v = *(const float4*)(A + (size_t)grow * K + kb + kc4);
                } else {
                    const float* Ar = A + (size_t)grow * K;
                    if (kb + kc4 + 0 < K) v.x = Ar[kb + kc4 + 0];
                    if (kb + kc4 + 1 < K) v.y = Ar[kb + kc4 + 1];
                    if (kb + kc4 + 2 < K) v.z = Ar[kb + kc4 + 2];
                    if (kb + kc4 + 3 < K) v.w = Ar[kb + kc4 + 3];
                }
            }
            uint4 w;
            w.x = cvt_tf32(v.x); w.y = cvt_tf32(v.y);
            w.z = cvt_tf32(v.z); w.w = cvt_tf32(v.w);
            *(uint4*)&As[arow][kc4] = w;
        }
        // ---- stage B (64x16): 1 float4 per thread
        {
            int nrow = tid >> 2;
            int kc4 = (tid & 3) * 4;
            float4 v = make_float4(0.f, 0.f, 0.f, 0.f);
            if (nrow < N) {
                if (kb + kc4 + 3 < K) {
                    v = *(const float4*)(B + (size_t)nrow * K + kb + kc4);
                } else {
                    const float* Br = B + (size_t)nrow * K;
                    if (kb + kc4 + 0 < K) v.x = Br[kb + kc4 + 0];
                    if (kb + kc4 + 1 < K) v.y = Br[kb + kc4 + 1];
                    if (kb + kc4 + 2 < K) v.z = Br[kb + kc4 + 2];
                    if (kb + kc4 + 3 < K) v.w = Br[kb + kc4 + 3];
                }
            }
            uint4 w;
            w.x = cvt_tf32(v.x); w.y = cvt_tf32(v.y);
            w.z = cvt_tf32(v.z); w.w = cvt_tf32(v.w);
            *(uint4*)&Bs[nrow][kc4] = w;
        }
        __syncthreads();

#pragma unroll
        for (int s = 0; s < BK; s += 8) {
            uint32_t af[2][4], bf[4][2];
#pragma unroll
            for (int mt = 0; mt < 2; mt++) {
                int mb = wm0 + mt * 16 + g;
                af[mt][0] = As[mb][s + q];
                af[mt][1] = As[mb + 8][s + q];
                af[mt][2] = As[mb][s + q + 4];
                af[mt][3] = As[mb + 8][s + q + 4];
            }
#pragma unroll
            for (int nt = 0; nt < 4; nt++) {
                int nb = wn0 + nt * 8 + g;
                bf[nt][0] = Bs[nb][s + q];
                bf[nt][1] = Bs[nb][s + q + 4];
            }
#pragma unroll
            for (int mt = 0; mt < 2; mt++)
#pragma unroll
                for (int nt = 0; nt < 4; nt++)
                    MMA_TF32(d[mt][nt], af[mt], bf[nt]);
        }
        __syncthreads();
    }

    // ---- epilogue: thread owns (row g, row g+8) x col (2q, 2q+1) per tile
    float betav = 0.0f;
    if (MODE == 1) betav = betap[0];

#pragma unroll
    for (int mt = 0; mt < 2; mt++) {
#pragma unroll
        for (int nt = 0; nt < 4; nt++) {
            int col = wn0 + nt * 8 + 2 * q;
            if (MODE == 2 && col + 1 >= N) continue;
            float2 extv = make_float2(0.f, 0.f);
            if (MODE == 1) extv = *(const float2*)&ext[col];
#pragma unroll
            for (int half = 0; half < 2; half++) {
                int row = bm0 + wm0 + mt * 16 + g + half * 8;
                if (row >= M) continue;
                float ox = d[mt][nt][2 * half];
                float oy = d[mt][nt][2 * half + 1];
                if (MODE == 0) {
                    *(float2*)&g_h[(size_t)row * HIDDEN + col]  = make_float2(ox, oy);
                    *(float2*)&g_x0[(size_t)row * HIDDEN + col] = make_float2(ox, oy);
                    store_bf2(row, col, ox, oy);
                } else if (MODE == 1) {
                    float2 hv = *(const float2*)&g_h[(size_t)row * HIDDEN + col];
                    float2 xv = *(const float2*)&g_x0[(size_t)row * HIDDEN + col];
                    float ux = hv.x + STEP_F * fmaxf(ox - hv.x * extv.x + xv.x * betav, 0.0f);
                    float uy = hv.y + STEP_F * fmaxf(oy - hv.y * extv.y + xv.y * betav, 0.0f);
                    *(float2*)&g_h[(size_t)row * HIDDEN + col] = make_float2(ux, uy);
                    store_bf2(row, col, ux, uy);
                } else {
                    *(float2*)&Cout[(size_t)row * N + col] = make_float2(ox, oy);
                }
            }
        }
    }
}

// ---------------- launch ----------------
extern "C" void kernel_launch(void* const* d_in, const int* in_sizes, int n_in,
                              void* d_out, int out_size) {
    const float* x    = (const float*)d_in[0];   // [50000, 500]
    const int*   ei   = (const int*)  d_in[1];   // [2, 1600000]
    const float* enc  = (const float*)d_in[2];   // [64, 500]
    const float* dec  = (const float*)d_in[3];   // [40, 64]
    const float* ext  = (const float*)d_in[4];   // [1, 64]
    const float* beta = (const float*)d_in[5];   // [1]
    const float* pw   = (const float*)d_in[6];   // [64, 66]
    float* out = (float*)d_out;                  // [50000, 40]

    const int* erow = ei;
    const int* ecol = ei + N_EDGES;

    // fork: CSR preprocessing on side stream, encoder GEMM concurrently on main
    cudaStream_t s2;
    cudaStreamCreateWithFlags(&s2, cudaStreamNonBlocking);
    cudaEvent_t evF, evJ;
    cudaEventCreateWithFlags(&evF, cudaEventDisableTiming);
    cudaEventCreateWithFlags(&evJ, cudaEventDisableTiming);

    cudaEventRecord(evF, 0);
    cudaStreamWaitEvent(s2, evF, 0);

    // --- side stream: graph preprocessing (CSR by destination) + W_eff
    zero_counts<<<(N_NODES + 255) / 256, 256, 0, s2>>>();
    count_deg<<<(N_EDGES + 255) / 256, 256, 0, s2>>>(ecol);
    deg_inv_kernel<<<(N_NODES + 255) / 256, 256, 0, s2>>>();
    scan1<<<SCAN_NBLK, SCAN_BLK, 0, s2>>>();
    scan2<<<1, 32, 0, s2>>>();
    scan3<<<(N_NODES + 255) / 256, 256, 0, s2>>>();
    fill_csr<<<(N_EDGES + 255) / 256, 256, 0, s2>>>(erow, ecol);
    weff_kernel<<<1, 64, 0, s2>>>(pw);
    cudaEventRecord(evJ, s2);

    int ggrid = (N_NODES + BM - 1) / BM;

    // --- main stream: encoder h = x0 = x @ enc_w^T (+ bf16 mirror)
    gemm_mma<0><<<ggrid, 256>>>(x, enc, nullptr, N_NODES, HIDDEN, NUM_FEATURES,
                                nullptr, nullptr);

    // join
    cudaStreamWaitEvent(0, evJ, 0);

    // 4 propagation layers
    for (int l = 0; l < NUM_LAYERS; l++) {
        gather_kernel<<<(N_NODES * 32 + 255) / 256, 256>>>();
        gemm_mma<1><<<ggrid, 256>>>(nullptr, nullptr, nullptr,
                                    N_NODES, HIDDEN, HIDDEN, ext, beta);
    }

    // decoder: out = h @ dec_w^T
    gemm_mma<2><<<ggrid, 256>>>(nullptr, dec, out, N_NODES, NUM_CLASSES, HIDDEN,
                                nullptr, nullptr);
    // NOTE: s2/evF/evJ intentionally not destroyed — destroying a stream that
    // participates in an active graph capture invalidates the capture.
    // kernel_launch is invoked only a handful of times (correctness + capture),
    // so the leaked handles are bounded and allocation-guard-safe.
}

// round 14
// speedup vs baseline: 1.0107x; 1.0107x over previous
#include <cuda_runtime.h>
#include <cuda_bf16.h>
#include <cstdint>

#define N_NODES 50000
#define N_EDGES 1600000
#define NUM_FEATURES 500
#define HIDDEN 64
#define NUM_CLASSES 40
#define NUM_LAYERS 4
#define STEP_F 0.1f

#define SCAN_BLK 1024
#define SCAN_NBLK ((N_NODES + SCAN_BLK - 1) / SCAN_BLK)   // 49

// ---------------- device scratch (static, allocation-free) ----------------
__device__ float g_h[N_NODES * HIDDEN];
__device__ float g_x0[N_NODES * HIDDEN];
__device__ float g_agg[N_NODES * HIDDEN];
__device__ __align__(128) __nv_bfloat162 g_hbf[N_NODES * (HIDDEN / 2)];  // bf16 mirror of h
__device__ unsigned long long g_srccoef[N_EDGES];   // packed {src, coef}
__device__ int   g_rowptr[N_NODES + 1];
__device__ int   g_degcnt[N_NODES];
__device__ int   g_fill[N_NODES];
__device__ float g_deginv[N_NODES];
__device__ float g_W[HIDDEN * HIDDEN];
__device__ int   g_blocksums[SCAN_NBLK];
__device__ int   g_blockoff[SCAN_NBLK];

// ---------------- graph preprocessing ----------------
__global__ void zero_counts() {
    int i = blockIdx.x * blockDim.x + threadIdx.x;
    if (i < N_NODES) { g_degcnt[i] = 0; g_fill[i] = 0; }
}

__global__ void count_deg(const int* __restrict__ col) {
    int e = blockIdx.x * blockDim.x + threadIdx.x;
    if (e < N_EDGES) atomicAdd(&g_degcnt[col[e]], 1);
}

__global__ void deg_inv_kernel() {
    int i = blockIdx.x * blockDim.x + threadIdx.x;
    if (i < N_NODES) {
        int c = g_degcnt[i];
        g_deginv[i] = (c > 0) ? rsqrtf((float)c) : 0.0f;
    }
}

// ---- multi-block exclusive scan of g_degcnt -> g_rowptr ----
__global__ void scan1() {
    __shared__ int s[SCAN_BLK];
    int b = blockIdx.x, t = threadIdx.x;
    int i = b * SCAN_BLK + t;
    int v = (i < N_NODES) ? g_degcnt[i] : 0;
    s[t] = v;
    __syncthreads();
#pragma unroll
    for (int off = 1; off < SCAN_BLK; off <<= 1) {
        int tv = 0;
        if (t >= off) tv = s[t - off];
        __syncthreads();
        if (t >= off) s[t] += tv;
        __syncthreads();
    }
    if (i < N_NODES) g_rowptr[i] = s[t] - v;     // block-local exclusive
    if (t == SCAN_BLK - 1) g_blocksums[b] = s[t];
}

__global__ void scan2() {
    if (threadIdx.x == 0) {
        int run = 0;
        for (int b = 0; b < SCAN_NBLK; b++) {
            g_blockoff[b] = run;
            run += g_blocksums[b];
        }
        g_rowptr[N_NODES] = run;
    }
}

__global__ void scan3() {
    int i = blockIdx.x * blockDim.x + threadIdx.x;
    if (i < N_NODES) g_rowptr[i] += g_blockoff[i >> 10];
}

__global__ void fill_csr(const int* __restrict__ row, const int* __restrict__ col) {
    int e = blockIdx.x * blockDim.x + threadIdx.x;
    if (e >= N_EDGES) return;
    int v = col[e];
    int r = row[e];
    int slot = g_rowptr[v] + atomicAdd(&g_fill[v], 1);
    float cf = g_deginv[r] * g_deginv[v];
    g_srccoef[slot] = (unsigned long long)(unsigned)r
                    | ((unsigned long long)__float_as_uint(cf) << 32);
}

// ---------------- pairwise weight: W_eff = sym(triu(pw,1)) + diag(q*rowsum|W|+r)
__global__ void weff_kernel(const float* __restrict__ pw) {
    int i = threadIdx.x;
    if (i >= HIDDEN) return;
    float q  = pw[i * (HIDDEN + 2) + HIDDEN];
    float rr = pw[i * (HIDDEN + 2) + HIDDEN + 1];
    float s = 0.0f;
    for (int j = 0; j < HIDDEN; j++) {
        float w = 0.0f;
        if (i < j)      w = pw[i * (HIDDEN + 2) + j];
        else if (i > j) w = pw[j * (HIDDEN + 2) + i];
        s += fabsf(w);
        g_W[i * HIDDEN + j] = w;
    }
    g_W[i * HIDDEN + i] = q * s + rr;
}

// ---------------- edge aggregation: agg[v] = sum coef * h_bf16[src]
// one warp per node; 32 lanes cover the 64-bf16 row (128B = ONE cache line).
__global__ void gather_kernel() {
    int gw   = (blockIdx.x * blockDim.x + threadIdx.x) >> 5;
    int lane = threadIdx.x & 31;
    if (gw >= N_NODES) return;
    int beg = g_rowptr[gw];
    int end = g_rowptr[gw + 1];
    float2 acc = make_float2(0.0f, 0.0f);
    const __nv_bfloat162* __restrict__ hb = g_hbf;
    int e = beg;
    for (; e + 7 < end; e += 8) {
        unsigned long long p[8];
        __nv_bfloat162 b[8];
#pragma unroll
        for (int i = 0; i < 8; i++) p[i] = __ldg(&g_srccoef[e + i]);
#pragma unroll
        for (int i = 0; i < 8; i++)
            b[i] = __ldg(hb + (size_t)(unsigned)(p[i] & 0xffffffffu) * 32 + lane);
#pragma unroll
        for (int i = 0; i < 8; i++) {
            float cf = __uint_as_float((unsigned)(p[i] >> 32));
            float2 v = __bfloat1622float2(b[i]);
            acc.x += cf * v.x;
            acc.y += cf * v.y;
        }
    }
    for (; e < end; e++) {
        unsigned long long p0 = __ldg(&g_srccoef[e]);
        __nv_bfloat162 b0 = __ldg(hb + (size_t)(unsigned)(p0 & 0xffffffffu) * 32 + lane);
        float c0 = __uint_as_float((unsigned)(p0 >> 32));
        float2 v0 = __bfloat1622float2(b0);
        acc.x += c0 * v0.x; acc.y += c0 * v0.y;
    }
    *(float2*)(g_agg + (size_t)gw * HIDDEN + lane * 2) = acc;
}

// ---------------- tf32 tensor-core GEMM: C[M,N] = A[M,K] @ B[N,K]^T
// mma.sync.m16n8k8, 256 threads, warp grid 4(M)x2(N), warp tile 32x32.
// smem: As[m][BK+4], Bs[n][BK+4] (stride 20 words -> conflict-free frag loads).
// MODE 0: encoder (A=x, B=enc_w)   -> writes g_h, g_x0, g_hbf
// MODE 1: layer   (A=g_agg, B=g_W) -> g_h += STEP*relu(acc - h*ext + x0*beta); also g_hbf
// MODE 2: decoder (A=g_h, B=dec_w) -> writes Cout
#define BM 128
#define BN 64
#define BK 16
#define KS (BK + 4)    // smem k-stride (20 words)

__device__ __forceinline__ uint32_t cvt_tf32(float v) {
    uint32_t u;
    asm("cvt.rna.tf32.f32 %0, %1;" : "=r"(u) : "f"(v));
    return u;
}

#define MMA_TF32(d, a, b)                                              \
    asm volatile(                                                      \
        "mma.sync.aligned.m16n8k8.row.col.f32.tf32.tf32.f32 "          \
        "{%0,%1,%2,%3}, {%4,%5,%6,%7}, {%8,%9}, {%0,%1,%2,%3};"        \
        : "+f"(d[0]), "+f"(d[1]), "+f"(d[2]), "+f"(d[3])               \
        : "r"(a[0]), "r"(a[1]), "r"(a[2]), "r"(a[3]),                  \
          "r"(b[0]), "r"(b[1]))

__device__ __forceinline__ void store_bf2(int row, int col, float x, float y) {
    __nv_bfloat162 bb = __floats2bfloat162_rn(x, y);
    g_hbf[(size_t)row * 32 + (col >> 1)] = bb;
}

template <int MODE>
__global__ void __launch_bounds__(256)
gemm_mma(const float* __restrict__ Ap, const float* __restrict__ Bp,
         float* __restrict__ Cout,
         int M, int N, int K,
         const float* __restrict__ ext, const float* __restrict__ betap) {
    __shared__ __align__(16) uint32_t As[BM][KS];
    __shared__ __align__(16) uint32_t Bs[BN][KS];

    const float* A = (MODE == 0) ? Ap : ((MODE == 1) ? (const float*)g_agg : (const float*)g_h);
    const float* B = (MODE == 1) ? (const float*)g_W : Bp;

    int tid  = threadIdx.x;
    int warp = tid >> 5;
    int lane = tid & 31;
    int q = lane & 3;          // k-quad
    int g = lane >> 2;         // group row/col
    int warpM = warp & 3;      // 4 warps along M
    int warpN = warp >> 2;     // 2 warps along N
    int wm0 = warpM * 32;
    int wn0 = warpN * 32;
    int bm0 = blockIdx.x * BM;

    float d[2][4][4];
#pragma unroll
    for (int mt = 0; mt < 2; mt++)
#pragma unroll
        for (int nt = 0; nt < 4; nt++)
#pragma unroll
            for (int i = 0; i < 4; i++) d[mt][nt][i] = 0.0f;

    for (int kb = 0; kb < K; kb += BK) {
        // ---- stage A (128x16): 2 float4 per thread, cvt to tf32, STS.128
#pragma unroll
        for (int it = 0; it < 2; it++) {
            int j = tid + it * 256;          // 0..511 float4 slots
            int arow = j >> 2;
            int kc4 = (j & 3) * 4;
            int grow = bm0 + arow;
            float4 v = make_float4(0.f, 0.f, 0.f, 0.f);
            if (grow < M) {
                if (kb + kc4 + 3 < K) {
                    v = *(const float4*)(A + (size_t)grow * K + kb + kc4);
                } else {
                    const float* Ar = A + (size_t)grow * K;
                    if (kb + kc4 + 0 < K) v.x = Ar[kb + kc4 + 0];
                    if (kb + kc4 + 1 < K) v.y = Ar[kb + kc4 + 1];
                    if (kb + kc4 + 2 < K) v.z = Ar[kb + kc4 + 2];
                    if (kb + kc4 + 3 < K) v.w = Ar[kb + kc4 + 3];
                }
            }
            uint4 w;
            w.x = cvt_tf32(v.x); w.y = cvt_tf32(v.y);
            w.z = cvt_tf32(v.z); w.w = cvt_tf32(v.w);
            *(uint4*)&As[arow][kc4] = w;
        }
        // ---- stage B (64x16): 1 float4 per thread
        {
            int nrow = tid >> 2;
            int kc4 = (tid & 3) * 4;
            float4 v = make_float4(0.f, 0.f, 0.f, 0.f);
            if (nrow < N) {
                if (kb + kc4 + 3 < K) {
                    v = *(const float4*)(B + (size_t)nrow * K + kb + kc4);
                } else {
                    const float* Br = B + (size_t)nrow * K;
                    if (kb + kc4 + 0 < K) v.x = Br[kb + kc4 + 0];
                    if (kb + kc4 + 1 < K) v.y = Br[kb + kc4 + 1];
                    if (kb + kc4 + 2 < K) v.z = Br[kb + kc4 + 2];
                    if (kb + kc4 + 3 < K) v.w = Br[kb + kc4 + 3];
                }
            }
            uint4 w;
            w.x = cvt_tf32(v.x); w.y = cvt_tf32(v.y);
            w.z = cvt_tf32(v.z); w.w = cvt_tf32(v.w);
            *(uint4*)&Bs[nrow][kc4] = w;
        }
        __syncthreads();

#pragma unroll
        for (int s = 0; s < BK; s += 8) {
            uint32_t af[2][4], bf[4][2];
#pragma unroll
            for (int mt = 0; mt < 2; mt++) {
                int mb = wm0 + mt * 16 + g;
                af[mt][0] = As[mb][s + q];
                af[mt][1] = As[mb + 8][s + q];
                af[mt][2] = As[mb][s + q + 4];
                af[mt][3] = As[mb + 8][s + q + 4];
            }
#pragma unroll
            for (int nt = 0; nt < 4; nt++) {
                int nb = wn0 + nt * 8 + g;
                bf[nt][0] = Bs[nb][s + q];
                bf[nt][1] = Bs[nb][s + q + 4];
            }
#pragma unroll
            for (int mt = 0; mt < 2; mt++)
#pragma unroll
                for (int nt = 0; nt < 4; nt++)
                    MMA_TF32(d[mt][nt], af[mt], bf[nt]);
        }
        __syncthreads();
    }

    // ---- epilogue: thread owns (row g, row g+8) x col (2q, 2q+1) per tile
    float betav = 0.0f;
    if (MODE == 1) betav = betap[0];

#pragma unroll
    for (int mt = 0; mt < 2; mt++) {
#pragma unroll
        for (int nt = 0; nt < 4; nt++) {
            int col = wn0 + nt * 8 + 2 * q;
            if (MODE == 2 && col + 1 >= N) continue;
            float2 extv = make_float2(0.f, 0.f);
            if (MODE == 1) extv = *(const float2*)&ext[col];
#pragma unroll
            for (int half = 0; half < 2; half++) {
                int row = bm0 + wm0 + mt * 16 + g + half * 8;
                if (row >= M) continue;
                float ox = d[mt][nt][2 * half];
                float oy = d[mt][nt][2 * half + 1];
                if (MODE == 0) {
                    *(float2*)&g_h[(size_t)row * HIDDEN + col]  = make_float2(ox, oy);
                    *(float2*)&g_x0[(size_t)row * HIDDEN + col] = make_float2(ox, oy);
                    store_bf2(row, col, ox, oy);
                } else if (MODE == 1) {
                    float2 hv = *(const float2*)&g_h[(size_t)row * HIDDEN + col];
                    float2 xv = *(const float2*)&g_x0[(size_t)row * HIDDEN + col];
                    float ux = hv.x + STEP_F * fmaxf(ox - hv.x * extv.x + xv.x * betav, 0.0f);
                    float uy = hv.y + STEP_F * fmaxf(oy - hv.y * extv.y + xv.y * betav, 0.0f);
                    *(float2*)&g_h[(size_t)row * HIDDEN + col] = make_float2(ux, uy);
                    store_bf2(row, col, ux, uy);
                } else {
                    *(float2*)&Cout[(size_t)row * N + col] = make_float2(ox, oy);
                }
            }
        }
    }
}

// ---------------- launch ----------------
extern "C" void kernel_launch(void* const* d_in, const int* in_sizes, int n_in,
                              void* d_out, int out_size) {
    const float* x    = (const float*)d_in[0];   // [50000, 500]
    const int*   ei   = (const int*)  d_in[1];   // [2, 1600000]
    const float* enc  = (const float*)d_in[2];   // [64, 500]
    const float* dec  = (const float*)d_in[3];   // [40, 64]
    const float* ext  = (const float*)d_in[4];   // [1, 64]
    const float* beta = (const float*)d_in[5];   // [1]
    const float* pw   = (const float*)d_in[6];   // [64, 66]
    float* out = (float*)d_out;                  // [50000, 40]

    const int* erow = ei;
    const int* ecol = ei + N_EDGES;

    // fork: CSR preprocessing on side stream, encoder GEMM concurrently on main
    cudaStream_t s2;
    cudaStreamCreateWithFlags(&s2, cudaStreamNonBlocking);
    cudaEvent_t evF, evJ;
    cudaEventCreateWithFlags(&evF, cudaEventDisableTiming);
    cudaEventCreateWithFlags(&evJ, cudaEventDisableTiming);

    cudaEventRecord(evF, 0);
    cudaStreamWaitEvent(s2, evF, 0);

    // --- side stream: graph preprocessing (CSR by destination) + W_eff
    zero_counts<<<(N_NODES + 255) / 256, 256, 0, s2>>>();
    count_deg<<<(N_EDGES + 255) / 256, 256, 0, s2>>>(ecol);
    deg_inv_kernel<<<(N_NODES + 255) / 256, 256, 0, s2>>>();
    scan1<<<SCAN_NBLK, SCAN_BLK, 0, s2>>>();
    scan2<<<1, 32, 0, s2>>>();
    scan3<<<(N_NODES + 255) / 256, 256, 0, s2>>>();
    fill_csr<<<(N_EDGES + 255) / 256, 256, 0, s2>>>(erow, ecol);
    weff_kernel<<<1, 64, 0, s2>>>(pw);
    cudaEventRecord(evJ, s2);

    int ggrid = (N_NODES + BM - 1) / BM;

    // --- main stream: encoder h = x0 = x @ enc_w^T (+ bf16 mirror)
    gemm_mma<0><<<ggrid, 256>>>(x, enc, nullptr, N_NODES, HIDDEN, NUM_FEATURES,
                                nullptr, nullptr);

    // join
    cudaStreamWaitEvent(0, evJ, 0);

    // 4 propagation layers
    for (int l = 0; l < NUM_LAYERS; l++) {
        gather_kernel<<<(N_NODES * 32 + 255) / 256, 256>>>();
        gemm_mma<1><<<ggrid, 256>>>(nullptr, nullptr, nullptr,
                                    N_NODES, HIDDEN, HIDDEN, ext, beta);
    }

    // decoder: out = h @ dec_w^T
    gemm_mma<2><<<ggrid, 256>>>(nullptr, dec, out, N_NODES, NUM_CLASSES, HIDDEN,
                                nullptr, nullptr);
    // NOTE: s2/evF/evJ intentionally not destroyed — destroying a stream that
    // participates in an active graph capture invalidates the capture.
    // kernel_launch is invoked only a handful of times (correctness + capture),
    // so the leaked handles are bounded and allocation-guard-safe.
}